// round 3
// baseline (speedup 1.0000x reference)
#include <cuda_runtime.h>
#include <math.h>

typedef unsigned long long ull;

#define BB 8
#define NN 64
#define HH 128
#define HEADS 4
#define HD 128
#define INNER 512
#define EE 8
#define NEdg 4032
#define LL 8
#define ROWS (BB*NN)   // 512
#define SPLITJ 4
#define JB (NN/SPLITJ) // 16
#define NB 128
#define NT 256

// ---------- persistent scratch (device globals; no allocations) ----------
__device__ float g_x[ROWS*HH];
__device__ float g_q[ROWS*INNER];
__device__ float g_k[ROWS*INNER];
__device__ float g_v[ROWS*INNER];
__device__ float g_skip[ROWS*HH];
__device__ float g_aggH[BB*HEADS*NN*HH];
__device__ float g_P[ROWS*EE];
__device__ float g_D[ROWS*EE];
__device__ int   g_eid[NN*NN];
__device__ unsigned g_bar_cnt;   // zero-initialized, self-resetting
__device__ unsigned g_bar_gen;   // monotonic generation (wrap-safe equality compare)

// ---------- packed f32x2 helpers (FFMA2: 2x fp32 FMA throughput) ----------
__device__ __forceinline__ ull fma2(ull a, ull b, ull c) {
    ull d; asm("fma.rn.f32x2 %0, %1, %2, %3;" : "=l"(d) : "l"(a), "l"(b), "l"(c)); return d;
}
__device__ __forceinline__ ull pk2(float x, float y) {
    ull r; unsigned a = __float_as_uint(x), b = __float_as_uint(y);
    asm("mov.b64 %0, {%1, %2};" : "=l"(r) : "r"(a), "r"(b)); return r;
}
__device__ __forceinline__ float f2sum(ull v) {
    unsigned a, b;
    asm("mov.b64 {%0, %1}, %2;" : "=r"(a), "=r"(b) : "l"(v));
    return __uint_as_float(a) + __uint_as_float(b);
}

// ---------- grid-wide barrier ----------
// Release: writer __threadfence before arrive. Acquire: __threadfence after the
// spin — gpu-scope fence emits CCTL.IVALL on sm_103a, invalidating this SM's L1
// so post-barrier loads of other CTAs' global writes see fresh data.
__device__ __forceinline__ void grid_sync() {
    __syncthreads();
    if (threadIdx.x == 0) {
        __threadfence();
        unsigned gen = *(volatile unsigned*)&g_bar_gen;
        if (atomicAdd(&g_bar_cnt, 1u) == NB - 1) {
            *(volatile unsigned*)&g_bar_cnt = 0u;
            __threadfence();
            *(volatile unsigned*)&g_bar_gen = gen + 1u;
        } else {
            while (*(volatile unsigned*)&g_bar_gen == gen) { __nanosleep(32); }
        }
        __threadfence();
    }
    __syncthreads();
}

__global__ void __launch_bounds__(NT, 1) mega(
    const float* __restrict__ noise, const float* __restrict__ edge_attr,
    const int* __restrict__ eidx,
    const float* __restrict__ fc1_w, const float* __restrict__ fc1_b,
    const float* __restrict__ qw, const float* __restrict__ qb,
    const float* __restrict__ kw, const float* __restrict__ kb,
    const float* __restrict__ vw, const float* __restrict__ vb,
    const float* __restrict__ ew,
    const float* __restrict__ sw, const float* __restrict__ sb,
    const float* __restrict__ atom_w, const float* __restrict__ atom_b,
    const float* __restrict__ other_w, const float* __restrict__ other_b,
    const float* __restrict__ efw, const float* __restrict__ efb,
    float* __restrict__ out)
{
    __shared__ __align__(16) float smem[10560];   // 42.2KB union across phases
    const int t = threadIdx.x, blk = blockIdx.x;

    // ================= init: x = relu(noise@fc1+b) broadcast; eid LUT =================
    if (blk < BB && t < HH) {
        float acc = fc1_b[t];
        #pragma unroll 4
        for (int i = 0; i < 128; i++) acc += noise[blk*128 + i] * fc1_w[i*HH + t];
        acc = fmaxf(acc, 0.f);
        for (int n = 0; n < NN; n++) g_x[(blk*NN + n)*HH + t] = acc;
    }
    for (int e = blk*NT + t; e < NEdg; e += NB*NT)
        g_eid[eidx[e]*NN + eidx[NEdg + e]] = e;
    grid_sync();

    for (int l = 0; l < LL; l++) {
        // ================= proj: [512,128] @ [qw|kw|vw|sw] (FMA2 k-packed) =================
        {
            float* As = smem;            // [64 rows][20] (16 k + pad), row-major
            float* Bs = smem + 1280;     // [64 cols][20]
            const int tx = t & 15, ty = t >> 4;
            for (int job = blk; job < 208; job += NB) {
                int ct = job % 26, rt = job / 26;
                const float *W, *bias; int ld, coff; float* outp;
                if (ct < 8)       { W = qw + l*HH*INNER; bias = qb + l*INNER; ld = INNER; coff = ct*64;      outp = g_q;   }
                else if (ct < 16) { W = kw + l*HH*INNER; bias = kb + l*INNER; ld = INNER; coff = (ct-8)*64;  outp = g_k;   }
                else if (ct < 24) { W = vw + l*HH*INNER; bias = vb + l*INNER; ld = INNER; coff = (ct-16)*64; outp = g_v;   }
                else              { W = sw + l*HH*HH;    bias = sb + l*HH;    ld = HH;    coff = (ct-24)*64; outp = g_skip;}
                int r0 = rt*64;
                ull acc[4][4];
                #pragma unroll
                for (int r = 0; r < 4; r++)
                    #pragma unroll
                    for (int c = 0; c < 4; c++) acc[r][c] = 0ull;
                for (int k0 = 0; k0 < 128; k0 += 16) {
                    int arow = t >> 2, akq = (t & 3) << 2;
                    float4 a4 = *(const float4*)&g_x[(r0+arow)*HH + k0 + akq];
                    *(float4*)&As[arow*20 + akq] = a4;   // 80B rows, 16B aligned
                    int bkk = t >> 4, bn = (t & 15) << 2;
                    float4 b4 = *(const float4*)&W[(k0+bkk)*ld + coff + bn];
                    Bs[(bn+0)*20+bkk]=b4.x; Bs[(bn+1)*20+bkk]=b4.y;
                    Bs[(bn+2)*20+bkk]=b4.z; Bs[(bn+3)*20+bkk]=b4.w;
                    __syncthreads();
                    #pragma unroll
                    for (int kp = 0; kp < 8; kp++) {
                        ull a2[4], b2[4];
                        #pragma unroll
                        for (int r = 0; r < 4; r++) a2[r] = *(const ull*)&As[(ty*4+r)*20 + kp*2];
                        #pragma unroll
                        for (int c = 0; c < 4; c++) b2[c] = *(const ull*)&Bs[(tx*4+c)*20 + kp*2];
                        #pragma unroll
                        for (int r = 0; r < 4; r++)
                            #pragma unroll
                            for (int c = 0; c < 4; c++) acc[r][c] = fma2(a2[r], b2[c], acc[r][c]);
                    }
                    __syncthreads();
                }
                #pragma unroll
                for (int r = 0; r < 4; r++)
                    #pragma unroll
                    for (int c = 0; c < 4; c++) {
                        int row = r0 + ty*4 + r, col = coff + tx*4 + c;
                        outp[row*ld + col] = f2sum(acc[r][c]) + bias[col];
                    }
            }
        }
        grid_sync();

        // ================= attn: one (graph, head, dst-quarter) per block =================
        {
            float* sU  = smem;            // 8192: (Qc,Kc) chunks, then full V
            float* sS  = smem + 8192;     // [16][68]
            float* sEw = smem + 9280;     // [8][128]
            float* sQE = smem + 10304;    // [16][8]
            float* sAE = smem + 10432;    // [16][8]
            int jseg = blk % SPLITJ;
            int h = (blk / SPLITJ) % HEADS;
            int b = blk / (SPLITJ*HEADS);
            int jbase = jseg * JB;
            const float scale = 0.08838834764831845f;  // 1/sqrt(128)

            for (int idx = t; idx < EE*HD; idx += NT)
                sEw[idx] = ew[((size_t)l*EE + (idx>>7))*INNER + h*HD + (idx & 127)];

            int jg = t >> 5, ig = t & 31;
            ull s00=0, s01=0, s10=0, s11=0;
            float qeacc = 0.f;
            float* sQc = sU;              // [16][32]
            float* sKc = sU + JB*32;      // [64][32]
            for (int dc = 0; dc < 4; dc++) {
                int d0 = dc*32;
                __syncthreads();
                for (int idx = t; idx < JB*32; idx += NT)
                    sQc[idx] = g_q[(b*NN + jbase + (idx>>5))*INNER + h*HD + d0 + (idx & 31)];
                for (int idx = t; idx < NN*32; idx += NT)
                    sKc[idx] = g_k[(b*NN + (idx>>5))*INNER + h*HD + d0 + (idx & 31)];
                __syncthreads();
                #pragma unroll
                for (int dd = 0; dd < 16; dd++) {
                    ull q0 = *(const ull*)&sQc[(jg*2+0)*32 + dd*2];
                    ull q1 = *(const ull*)&sQc[(jg*2+1)*32 + dd*2];
                    ull kk0 = *(const ull*)&sKc[(ig*2+0)*32 + dd*2];
                    ull kk1 = *(const ull*)&sKc[(ig*2+1)*32 + dd*2];
                    s00 = fma2(q0,kk0,s00); s01 = fma2(q0,kk1,s01);
                    s10 = fma2(q1,kk0,s10); s11 = fma2(q1,kk1,s11);
                }
                if (t < JB*EE) {
                    int jj = t >> 3, f = t & 7;
                    float s = 0.f;
                    #pragma unroll
                    for (int dd = 0; dd < 32; dd++) s += sQc[jj*32+dd] * sEw[f*128 + d0+dd];
                    qeacc += s;
                }
            }
            __syncthreads();
            if (t < JB*EE) sQE[t] = qeacc;
            __syncthreads();

            float accs[2][2] = {{f2sum(s00), f2sum(s01)}, {f2sum(s10), f2sum(s11)}};
            #pragma unroll
            for (int rr = 0; rr < 2; rr++)
                #pragma unroll
                for (int cc = 0; cc < 2; cc++) {
                    int jl = jg*2 + rr, j = jbase + jl, i = ig*2 + cc;
                    float sc;
                    if (i == j) sc = -1e30f;
                    else {
                        int eix = g_eid[i*NN + j];
                        const float* ea = edge_attr + ((size_t)b*NEdg + eix)*EE;
                        float bsum = 0.f;
                        #pragma unroll
                        for (int f = 0; f < EE; f++) bsum += ea[f] * sQE[jl*8+f];
                        sc = (accs[rr][cc] + bsum) * scale;
                    }
                    sS[jl*68 + i] = sc;
                }
            __syncthreads();

            // softmax per dst row (16 lanes per row)
            {
                int row = t >> 4, lane = t & 15;
                float m = -1e30f;
                for (int i = lane; i < NN; i += 16) m = fmaxf(m, sS[row*68+i]);
                #pragma unroll
                for (int o = 1; o < 16; o <<= 1) m = fmaxf(m, __shfl_xor_sync(0xffffffffu, m, o));
                float sum = 0.f;
                for (int i = lane; i < NN; i += 16) { float e = __expf(sS[row*68+i]-m); sS[row*68+i]=e; sum += e; }
                #pragma unroll
                for (int o = 1; o < 16; o <<= 1) sum += __shfl_xor_sync(0xffffffffu, sum, o);
                float inv = 1.f / sum;
                for (int i = lane; i < NN; i += 16) sS[row*68+i] *= inv;
            }
            __syncthreads();

            // aggE[j,f] = sum_i alpha[j,i] * edge_attr[i->j, f]
            {
                int row = t >> 4, lane = t & 15;
                int j = jbase + row;
                float ae[EE] = {};
                for (int i = lane; i < NN; i += 16) {
                    if (i == j) continue;
                    float a = sS[row*68+i];
                    const float* ea = edge_attr + ((size_t)b*NEdg + g_eid[i*NN+j])*EE;
                    #pragma unroll
                    for (int f = 0; f < EE; f++) ae[f] += a * ea[f];
                }
                #pragma unroll
                for (int f = 0; f < EE; f++)
                    #pragma unroll
                    for (int o = 1; o < 16; o <<= 1) ae[f] += __shfl_xor_sync(0xffffffffu, ae[f], o);
                if (lane == 0)
                    #pragma unroll
                    for (int f = 0; f < EE; f++) sAE[row*8+f] = ae[f];
            }
            __syncthreads();
            for (int idx = t; idx < NN*HD; idx += NT)
                sU[idx] = g_v[(b*NN + (idx>>7))*INNER + h*HD + (idx & 127)];
            __syncthreads();

            // agg[j,d] = alpha[j,:] @ V + aggE[j,:] @ eW   (16 j x 16 d-groups of 8)
            {
                int j = t >> 4;
                int d0 = (t & 15) * 8;
                ull a2[4] = {0ull,0ull,0ull,0ull};
                for (int i = 0; i < NN; i++) {
                    float al = sS[j*68+i];          // self edge contributes 0
                    ull al2 = pk2(al, al);
                    const float* vp = &sU[i*HD + d0];
                    a2[0] = fma2(al2, *(const ull*)(vp+0), a2[0]);
                    a2[1] = fma2(al2, *(const ull*)(vp+2), a2[1]);
                    a2[2] = fma2(al2, *(const ull*)(vp+4), a2[2]);
                    a2[3] = fma2(al2, *(const ull*)(vp+6), a2[3]);
                }
                #pragma unroll
                for (int f = 0; f < EE; f++) {
                    float aev = sAE[j*8+f];
                    ull ae2 = pk2(aev, aev);
                    const float* wp = &sEw[f*128 + d0];
                    a2[0] = fma2(ae2, *(const ull*)(wp+0), a2[0]);
                    a2[1] = fma2(ae2, *(const ull*)(wp+2), a2[1]);
                    a2[2] = fma2(ae2, *(const ull*)(wp+4), a2[2]);
                    a2[3] = fma2(ae2, *(const ull*)(wp+6), a2[3]);
                }
                ull* dst = (ull*)&g_aggH[((size_t)(b*HEADS+h)*NN + jbase + j)*HD + d0];
                dst[0]=a2[0]; dst[1]=a2[1]; dst[2]=a2[2]; dst[3]=a2[3];
            }
        }
        grid_sync();

        // ================= combine: x = relu(mean_h(agg) + skip) =================
        {
            int base = blk * 512;
            #pragma unroll
            for (int kq = 0; kq < 2; kq++) {
                int idx = base + kq*NT + t;
                int row = idx >> 7, d = idx & 127;
                int b = row >> 6, n = row & 63;
                float s = 0.f;
                #pragma unroll
                for (int h = 0; h < HEADS; h++)
                    s += g_aggH[((b*HEADS+h)*NN + n)*HH + d];
                g_x[idx] = fmaxf(s*0.25f + g_skip[idx], 0.f);
            }
        }
        grid_sync();
    }

    // ================= node head + P/D precompute (4 nodes per block) =================
    {
        float* xr   = smem;               // [4][128]
        float* outs = smem + 512;         // [4][40]
        float* red  = smem + 512 + 160;   // [4][2]
        int sub = t >> 6, tl = t & 63;
        int node = blk*4 + sub;
        xr[sub*128 + tl]      = g_x[node*128 + tl];
        xr[sub*128 + tl + 64] = g_x[node*128 + tl + 64];
        __syncthreads();
        if (tl < 40) {
            const float* xp = &xr[sub*128];
            float acc;
            if (tl < 9)       { acc = atom_b[tl];  for (int d = 0; d < HH; d++) acc += xp[d]*atom_w[d*9+tl]; }
            else if (tl < 24) { int c = tl-9;  acc = other_b[c]; for (int d = 0; d < HH; d++) acc += xp[d]*other_w[d*15+c]; }
            else if (tl < 32) { int f = tl-24; acc = 0.f; for (int d = 0; d < HH; d++) acc += xp[d]*efw[d*EE+f]; }
            else              { int f = tl-32; acc = 0.f; for (int d = 0; d < HH; d++) acc += xp[d]*efw[(128+d)*EE+f]; }
            outs[sub*40 + tl] = acc;
        }
        __syncthreads();
        if (tl == 0) {
            float m = -1e30f;
            for (int a = 0; a < 9; a++) m = fmaxf(m, outs[sub*40+a]);
            float s = 0.f;
            for (int a = 0; a < 9; a++) s += __expf(outs[sub*40+a]-m);
            red[sub*2] = m; red[sub*2+1] = s;
        }
        __syncthreads();
        if (tl < 9) {
            float p = __expf(outs[sub*40+tl]-red[sub*2]) / red[sub*2+1];
            out[node*24 + tl] = 1.f/(1.f + __expf(-p));
        } else if (tl < 24) {
            float o = 1.f/(1.f + __expf(-outs[sub*40+tl]));
            out[node*24 + tl] = 1.f/(1.f + __expf(-o));
        } else if (tl < 32) {
            g_P[node*EE + (tl-24)] = outs[sub*40+tl];
        } else if (tl < 40) {
            g_D[node*EE + (tl-32)] = outs[sub*40+tl];
        }
    }
    grid_sync();

    // ================= edge head: sigmoid(P[src] + D[dst] + b) =================
    {
        int eg = blk*252 + t;       // 128*252 = 32256 exactly
        if (t < 252) {
            int b = eg / NEdg, e = eg % NEdg;
            int s = eidx[e], d = eidx[NEdg + e];
            const float* P = &g_P[(b*NN + s)*EE];
            const float* D = &g_D[(b*NN + d)*EE];
            float* o = out + ROWS*24 + (size_t)eg*EE;
            #pragma unroll
            for (int f = 0; f < EE; f++) {
                float v = P[f] + D[f] + efb[f];
                o[f] = 1.f/(1.f + __expf(-v));
            }
        }
    }
}

extern "C" void kernel_launch(void* const* d_in, const int* in_sizes, int n_in,
                              void* d_out, int out_size) {
    const float* noise     = (const float*)d_in[0];
    const float* edge_attr = (const float*)d_in[1];
    const int*   edge_index= (const int*)  d_in[2];
    const float* fc1_w     = (const float*)d_in[3];
    const float* fc1_b     = (const float*)d_in[4];
    const float* q_w       = (const float*)d_in[5];
    const float* q_b       = (const float*)d_in[6];
    const float* k_w       = (const float*)d_in[7];
    const float* k_b       = (const float*)d_in[8];
    const float* v_w       = (const float*)d_in[9];
    const float* v_b       = (const float*)d_in[10];
    const float* e_w       = (const float*)d_in[11];
    const float* skip_w    = (const float*)d_in[12];
    const float* skip_b    = (const float*)d_in[13];
    const float* atom_w    = (const float*)d_in[14];
    const float* atom_b    = (const float*)d_in[15];
    const float* other_w   = (const float*)d_in[16];
    const float* other_b   = (const float*)d_in[17];
    const float* efw       = (const float*)d_in[18];
    const float* efb       = (const float*)d_in[19];
    float* out = (float*)d_out;

    mega<<<NB, NT>>>(noise, edge_attr, edge_index, fc1_w, fc1_b,
                     q_w, q_b, k_w, k_b, v_w, v_b, e_w, skip_w, skip_b,
                     atom_w, atom_b, other_w, other_b, efw, efb, out);
}

// round 4
// speedup vs baseline: 2.0947x; 2.0947x over previous
#include <cuda_runtime.h>
#include <math.h>

typedef unsigned long long ull;

#define BB 8
#define NN 64
#define HH 128
#define HEADS 4
#define HD 128
#define INNER 512
#define EE 8
#define NEdg 4032
#define LL 8
#define ROWS (BB*NN)   // 512
#define SPLITJ 8
#define JB (NN/SPLITJ) // 8
#define NT 256

// ---------- persistent scratch ----------
__device__ float g_x[ROWS*HH];
__device__ float g_q[ROWS*INNER];
__device__ float g_k[ROWS*INNER];
__device__ float g_v[ROWS*INNER];
__device__ float g_skip[ROWS*HH];
__device__ float g_aggH[BB*HEADS*NN*HH];
__device__ float g_P[ROWS*EE];
__device__ float g_D[ROWS*EE];
__device__ int   g_eid[NN*NN];

// ---------- packed f32x2 helpers ----------
__device__ __forceinline__ ull fma2(ull a, ull b, ull c) {
    ull d; asm("fma.rn.f32x2 %0, %1, %2, %3;" : "=l"(d) : "l"(a), "l"(b), "l"(c)); return d;
}
__device__ __forceinline__ ull pk2(float x, float y) {
    ull r; unsigned a = __float_as_uint(x), b = __float_as_uint(y);
    asm("mov.b64 %0, {%1, %2};" : "=l"(r) : "r"(a), "r"(b)); return r;
}
__device__ __forceinline__ float f2sum(ull v) {
    unsigned a, b;
    asm("mov.b64 {%0, %1}, %2;" : "=r"(a), "=r"(b) : "l"(v));
    return __uint_as_float(a) + __uint_as_float(b);
}

// ---------- init: x = relu(noise@fc1+b) broadcast; eid LUT ----------
__global__ void k_init(const float* __restrict__ noise, const float* __restrict__ fc1_w,
                       const float* __restrict__ fc1_b, const int* __restrict__ eidx) {
    int b = blockIdx.x, t = threadIdx.x;  // 8 x 128
    float acc = fc1_b[t];
    #pragma unroll 4
    for (int i = 0; i < 128; i++) acc += noise[b*128 + i] * fc1_w[i*HH + t];
    acc = fmaxf(acc, 0.f);
    for (int n = 0; n < NN; n++) g_x[(b*NN + n)*HH + t] = acc;
    for (int e = b*504 + t; e < (b+1)*504; e += 128) {
        int s = eidx[e], d = eidx[NEdg + e];
        g_eid[s*NN + d] = e;
    }
}

// ---------- proj: [512,128] @ [qw|kw|vw|sw]; FMA2, conflict-free tiles ----------
// grid (26, 8), 256 threads, BM=BN=64, BK=16
__global__ void k_proj(int l,
                       const float* __restrict__ qw, const float* __restrict__ qb,
                       const float* __restrict__ kw, const float* __restrict__ kb,
                       const float* __restrict__ vw, const float* __restrict__ vb,
                       const float* __restrict__ sw, const float* __restrict__ sb) {
    __shared__ float As[64][20];   // [row][k], pad to 20 -> 80B rows (8B aligned, 2-addr bcast)
    __shared__ float Bs[16][64];   // [k][col]
    int ct = blockIdx.x, rt = blockIdx.y;
    const float* W; const float* bias; int ld, coff; float* outp;
    if (ct < 8)       { W = qw + l*HH*INNER; bias = qb + l*INNER; ld = INNER; coff = ct*64;      outp = g_q;   }
    else if (ct < 16) { W = kw + l*HH*INNER; bias = kb + l*INNER; ld = INNER; coff = (ct-8)*64;  outp = g_k;   }
    else if (ct < 24) { W = vw + l*HH*INNER; bias = vb + l*INNER; ld = INNER; coff = (ct-16)*64; outp = g_v;   }
    else              { W = sw + l*HH*HH;    bias = sb + l*HH;    ld = HH;    coff = (ct-24)*64; outp = g_skip;}
    int t = threadIdx.x;
    int tx = t & 15, ty = t >> 4;
    ull acc[4][4];
    #pragma unroll
    for (int r = 0; r < 4; r++)
        #pragma unroll
        for (int c = 0; c < 4; c++) acc[r][c] = 0ull;
    int r0 = rt*64;
    for (int k0 = 0; k0 < 128; k0 += 16) {
        int arow = t >> 2, akq = (t & 3) << 2;
        float4 a4 = *(const float4*)&g_x[(r0+arow)*HH + k0 + akq];
        *(float4*)&As[arow][akq] = a4;
        int bkk = t >> 4, bn = (t & 15) << 2;
        float4 b4 = *(const float4*)&W[(k0+bkk)*ld + coff + bn];
        *(float4*)&Bs[bkk][bn] = b4;
        __syncthreads();
        #pragma unroll
        for (int kp = 0; kp < 8; kp++) {
            ull a2[4], b2[4];
            #pragma unroll
            for (int r = 0; r < 4; r++) a2[r] = *(const ull*)&As[ty*4+r][kp*2];
            #pragma unroll
            for (int c = 0; c < 4; c++) b2[c] = pk2(Bs[kp*2][tx*4+c], Bs[kp*2+1][tx*4+c]);
            #pragma unroll
            for (int r = 0; r < 4; r++)
                #pragma unroll
                for (int c = 0; c < 4; c++) acc[r][c] = fma2(a2[r], b2[c], acc[r][c]);
        }
        __syncthreads();
    }
    #pragma unroll
    for (int r = 0; r < 4; r++)
        #pragma unroll
        for (int c = 0; c < 4; c++) {
            int row = r0 + ty*4 + r, col = coff + tx*4 + c;
            outp[row*ld + col] = f2sum(acc[r][c]) + bias[col];
        }
}

// ---------- attn: one (graph, head, dst-octant) per block; conflict-free smem ----------
// grid = B*HEADS*SPLITJ = 256 blocks, 256 threads (8 warps, warp w owns dst row j = jbase+w)
__global__ void __launch_bounds__(NT) k_attn(int l, const float* __restrict__ edge_attr,
                                             const float* __restrict__ ew) {
    __shared__ float sQ[JB*HD];       // 1024
    __shared__ float sKV[NN*HD];      // 8192: K xor-swizzled, then V linear
    __shared__ float sS[JB][68];      // alpha
    __shared__ float sEw[EE*HD];      // 1024
    __shared__ float sQE[JB*EE];
    __shared__ float sAE[JB*EE];

    int blk = blockIdx.x;
    int jseg = blk & 7;
    int h = (blk >> 3) & 3;
    int b = blk >> 5;
    int jbase = jseg * JB;
    int t = threadIdx.x;
    int w = t >> 5, lane = t & 31;
    const float scale = 0.08838834764831845f;  // 1/sqrt(128)

    // eW [8][128] (one f-row per 128B) — float4 coalesced
    {
        int idx = t * 4;
        *(float4*)&sEw[idx] = *(const float4*)&ew[((size_t)l*EE + (idx >> 7))*INNER + h*HD + (idx & 127)];
    }
    // Q [8][128] linear (score reads are warp-broadcast)
    {
        int idx = t * 4;
        int row = idx >> 7, d = idx & 127;
        *(float4*)&sQ[idx] = *(const float4*)&g_q[(b*NN + jbase + row)*INNER + h*HD + d];
    }
    // K with word-level XOR swizzle: sKV[row*128 + (d ^ (row&31))]
    for (int q4 = t; q4 < NN*32; q4 += NT) {
        int row = q4 >> 5, dq = (q4 & 31) << 2;
        float4 v = *(const float4*)&g_k[(b*NN + row)*INNER + h*HD + dq];
        int rx = row & 31;
        float* base = &sKV[row*128];
        base[(dq+0) ^ rx] = v.x;
        base[(dq+1) ^ rx] = v.y;
        base[(dq+2) ^ rx] = v.z;
        base[(dq+3) ^ rx] = v.w;
    }
    __syncthreads();

    // ---- scores: warp w computes s(j=jbase+w, i) for i = lane, lane+32 ----
    const float* qrow = &sQ[w*HD];
    float acc1 = 0.f, acc2 = 0.f;
    {
        const float* k1p = &sKV[lane*128];
        const float* k2p = &sKV[(lane+32)*128];
        #pragma unroll 8
        for (int dd = 0; dd < 128; dd++) {
            int ds = dd ^ lane;          // conflict-free: bank = (dd^lane) distinct per lane
            float qv = qrow[dd];
            acc1 += qv * k1p[ds];
            acc2 += qv * k2p[ds];
        }
    }
    // ---- qe[j,f] = q[j]·eW[f] (warp-local, lane = (seg,f), staggered => conflict-free) ----
    {
        int f = lane & 7, seg = lane >> 3;
        const float* ewrow = &sEw[f*HD + seg*32];
        const float* qseg  = qrow + seg*32;
        float p = 0.f;
        #pragma unroll
        for (int i = 0; i < 32; i++) {
            int d = (i + lane) & 31;
            p += qseg[d] * ewrow[d];
        }
        p += __shfl_xor_sync(0xffffffffu, p, 8);
        p += __shfl_xor_sync(0xffffffffu, p, 16);
        if (lane < 8) sQE[w*8 + lane] = p;
    }
    __syncwarp();

    // ---- edge bias + mask + softmax + aggE (fully warp-local) ----
    int j = jbase + w;
    int i1 = lane, i2 = lane + 32;
    const float* eabase = edge_attr + (size_t)b * NEdg * EE;
    int e1 = (i1 == j) ? 0 : g_eid[i1*NN + j];
    int e2 = (i2 == j) ? 0 : g_eid[i2*NN + j];
    float4 ea1a = *(const float4*)&eabase[e1*EE];
    float4 ea1b = *(const float4*)&eabase[e1*EE + 4];
    float4 ea2a = *(const float4*)&eabase[e2*EE];
    float4 ea2b = *(const float4*)&eabase[e2*EE + 4];
    float ea1[8] = {ea1a.x, ea1a.y, ea1a.z, ea1a.w, ea1b.x, ea1b.y, ea1b.z, ea1b.w};
    float ea2[8] = {ea2a.x, ea2a.y, ea2a.z, ea2a.w, ea2b.x, ea2b.y, ea2b.z, ea2b.w};
    float bs1 = 0.f, bs2 = 0.f;
    #pragma unroll
    for (int f = 0; f < 8; f++) {
        float qe = sQE[w*8 + f];     // broadcast
        bs1 += ea1[f] * qe;
        bs2 += ea2[f] * qe;
    }
    float s1 = (i1 == j) ? -1e30f : (acc1 + bs1) * scale;
    float s2 = (i2 == j) ? -1e30f : (acc2 + bs2) * scale;
    float m = fmaxf(s1, s2);
    #pragma unroll
    for (int o = 1; o < 32; o <<= 1) m = fmaxf(m, __shfl_xor_sync(0xffffffffu, m, o));
    float x1 = __expf(s1 - m), x2 = __expf(s2 - m);
    float sum = x1 + x2;
    #pragma unroll
    for (int o = 1; o < 32; o <<= 1) sum += __shfl_xor_sync(0xffffffffu, sum, o);
    float inv = 1.f / sum;
    float al1 = x1 * inv, al2 = x2 * inv;
    sS[w][i1] = al1;
    sS[w][i2] = al2;
    // aggE[j,f] = sum_i alpha * ea  (ea already in regs; self has alpha=0)
    {
        float ae[8];
        #pragma unroll
        for (int f = 0; f < 8; f++) {
            float v = al1*ea1[f] + al2*ea2[f];
            #pragma unroll
            for (int o = 1; o < 32; o <<= 1) v += __shfl_xor_sync(0xffffffffu, v, o);
            ae[f] = v;
        }
        if (lane == 0) {
            #pragma unroll
            for (int f = 0; f < 8; f++) sAE[w*8 + f] = ae[f];
        }
    }
    __syncthreads();

    // ---- reload buffer with V (linear) ----
    for (int idx = t*4; idx < NN*HD; idx += NT*4) {
        int row = idx >> 7, d = idx & 127;
        *(float4*)&sKV[idx] = *(const float4*)&g_v[(b*NN + row)*INNER + h*HD + d];
    }
    __syncthreads();

    // ---- agg[j,d] = alpha[j,:] @ V + aggE[j,:] @ eW; lane owns d = lane*4 ----
    {
        int d0 = lane * 4;
        float ax = 0.f, ay = 0.f, az = 0.f, aw = 0.f;
        #pragma unroll 4
        for (int i = 0; i < NN; i++) {
            float al = sS[w][i];                        // broadcast
            float4 v = *(const float4*)&sKV[i*HD + d0]; // LDS.128 conflict-free
            ax += al*v.x; ay += al*v.y; az += al*v.z; aw += al*v.w;
        }
        #pragma unroll
        for (int f = 0; f < 8; f++) {
            float ae = sAE[w*8 + f];
            float4 wv = *(const float4*)&sEw[f*HD + d0];
            ax += ae*wv.x; ay += ae*wv.y; az += ae*wv.z; aw += ae*wv.w;
        }
        float4 r = {ax, ay, az, aw};
        *(float4*)&g_aggH[(((size_t)b*HEADS + h)*NN + jbase + w)*HD + d0] = r;
    }
}

// ---------- combine: x = relu(mean_h(agg) + skip) ----------
__global__ void k_combine() {   // grid 256, block 256 -> 65536 elems
    int idx = blockIdx.x*NT + threadIdx.x;
    int row = idx >> 7, d = idx & 127;
    int b = row >> 6, n = row & 63;
    float s = 0.f;
    #pragma unroll
    for (int h = 0; h < HEADS; h++)
        s += g_aggH[((b*HEADS + h)*NN + n)*HH + d];
    g_x[idx] = fmaxf(s*0.25f + g_skip[idx], 0.f);
}

// ---------- node head + P/D precompute ----------
__global__ void k_node(const float* __restrict__ atom_w, const float* __restrict__ atom_b,
                       const float* __restrict__ other_w, const float* __restrict__ other_b,
                       const float* __restrict__ efw, float* __restrict__ out) {
    __shared__ float xr[HH];
    __shared__ float outs[40];
    __shared__ float red[2];
    int node = blockIdx.x; int t = threadIdx.x;   // 512 x 64
    xr[t] = g_x[node*HH + t];
    xr[t+64] = g_x[node*HH + t + 64];
    __syncthreads();
    if (t < 40) {
        float acc;
        if (t < 9)       { acc = atom_b[t];       for (int d = 0; d < HH; d++) acc += xr[d]*atom_w[d*9 + t]; }
        else if (t < 24) { int c = t-9; acc = other_b[c]; for (int d = 0; d < HH; d++) acc += xr[d]*other_w[d*15 + c]; }
        else if (t < 32) { int f = t-24; acc = 0.f; for (int d = 0; d < HH; d++) acc += xr[d]*efw[d*EE + f]; }
        else             { int f = t-32; acc = 0.f; for (int d = 0; d < HH; d++) acc += xr[d]*efw[(128+d)*EE + f]; }
        outs[t] = acc;
    }
    __syncthreads();
    if (t == 0) {
        float m = -1e30f;
        for (int a = 0; a < 9; a++) m = fmaxf(m, outs[a]);
        float s = 0.f;
        for (int a = 0; a < 9; a++) s += __expf(outs[a]-m);
        red[0] = m; red[1] = s;
    }
    __syncthreads();
    if (t < 9) {
        float p = __expf(outs[t]-red[0]) / red[1];
        out[node*24 + t] = 1.f/(1.f + __expf(-p));
    } else if (t < 24) {
        float o = 1.f/(1.f + __expf(-outs[t]));
        out[node*24 + t] = 1.f/(1.f + __expf(-o));
    } else if (t < 32) {
        g_P[node*EE + (t-24)] = outs[t];
    } else if (t < 40) {
        g_D[node*EE + (t-32)] = outs[t];
    }
}

// ---------- edge head: sigmoid(P[src] + D[dst] + b) ----------
__global__ void k_edge(const int* __restrict__ eidx, const float* __restrict__ efb,
                       float* __restrict__ out) {
    int eg = blockIdx.x*NT + threadIdx.x;
    if (eg >= BB*NEdg) return;
    int b = eg / NEdg, e = eg % NEdg;
    int s = eidx[e], d = eidx[NEdg + e];
    const float* P = &g_P[(b*NN + s)*EE];
    const float* D = &g_D[(b*NN + d)*EE];
    float* o = out + (size_t)ROWS*24 + (size_t)eg*EE;
    #pragma unroll
    for (int f = 0; f < EE; f++) {
        float v = P[f] + D[f] + efb[f];
        o[f] = 1.f/(1.f + __expf(-v));
    }
}

extern "C" void kernel_launch(void* const* d_in, const int* in_sizes, int n_in,
                              void* d_out, int out_size) {
    const float* noise     = (const float*)d_in[0];
    const float* edge_attr = (const float*)d_in[1];
    const int*   edge_index= (const int*)  d_in[2];
    const float* fc1_w     = (const float*)d_in[3];
    const float* fc1_b     = (const float*)d_in[4];
    const float* q_w       = (const float*)d_in[5];
    const float* q_b       = (const float*)d_in[6];
    const float* k_w       = (const float*)d_in[7];
    const float* k_b       = (const float*)d_in[8];
    const float* v_w       = (const float*)d_in[9];
    const float* v_b       = (const float*)d_in[10];
    const float* e_w       = (const float*)d_in[11];
    const float* skip_w    = (const float*)d_in[12];
    const float* skip_b    = (const float*)d_in[13];
    const float* atom_w    = (const float*)d_in[14];
    const float* atom_b    = (const float*)d_in[15];
    const float* other_w   = (const float*)d_in[16];
    const float* other_b   = (const float*)d_in[17];
    const float* efw       = (const float*)d_in[18];
    const float* efb       = (const float*)d_in[19];
    float* out = (float*)d_out;

    k_init<<<8, 128>>>(noise, fc1_w, fc1_b, edge_index);
    for (int l = 0; l < LL; l++) {
        k_proj<<<dim3(26, 8), NT>>>(l, q_w, q_b, k_w, k_b, v_w, v_b, skip_w, skip_b);
        k_attn<<<BB*HEADS*SPLITJ, NT>>>(l, edge_attr, e_w);
        k_combine<<<256, NT>>>();
    }
    k_node<<<ROWS, 64>>>(atom_w, atom_b, other_w, other_b, efw, out);
    k_edge<<<126, NT>>>(edge_index, efb, out);
}

// round 5
// speedup vs baseline: 2.2209x; 1.0602x over previous
#include <cuda_runtime.h>
#include <math.h>

typedef unsigned long long ull;

#define BB 8
#define NN 64
#define HH 128
#define HEADS 4
#define HD 128
#define INNER 512
#define EE 8
#define NEdg 4032
#define LL 8
#define ROWS (BB*NN)   // 512
#define SPLITJ 8
#define JB (NN/SPLITJ) // 8
#define NB 256
#define NT 256

// ---------- persistent scratch ----------
__device__ float g_bufA[ROWS*HH];
__device__ float g_bufB[ROWS*HH];
__device__ float g_q[ROWS*INNER];
__device__ float g_k[ROWS*INNER];
__device__ float g_v[ROWS*INNER];
__device__ float g_P[ROWS*EE];
__device__ float g_D[ROWS*EE];
__device__ int   g_eid[NN*NN];
__device__ unsigned g_bar_cnt;   // zero-init; self-resetting
__device__ unsigned g_bar_gen;   // monotonic generation

// ---------- packed f32x2 helpers ----------
__device__ __forceinline__ ull fma2(ull a, ull b, ull c) {
    ull d; asm("fma.rn.f32x2 %0, %1, %2, %3;" : "=l"(d) : "l"(a), "l"(b), "l"(c)); return d;
}
__device__ __forceinline__ ull pk2(float x, float y) {
    ull r; unsigned a = __float_as_uint(x), b = __float_as_uint(y);
    asm("mov.b64 %0, {%1, %2};" : "=l"(r) : "r"(a), "r"(b)); return r;
}
__device__ __forceinline__ float f2sum(ull v) {
    unsigned a, b;
    asm("mov.b64 {%0, %1}, %2;" : "=r"(a), "=r"(b) : "l"(v));
    return __uint_as_float(a) + __uint_as_float(b);
}

// ---------- grid barrier (acquire fence = CCTL.IVALL -> L1 coherent reads after) ----------
__device__ __forceinline__ void grid_sync() {
    __syncthreads();
    if (threadIdx.x == 0) {
        __threadfence();
        unsigned gen = *(volatile unsigned*)&g_bar_gen;
        if (atomicAdd(&g_bar_cnt, 1u) == NB - 1) {
            *(volatile unsigned*)&g_bar_cnt = 0u;
            __threadfence();
            *(volatile unsigned*)&g_bar_gen = gen + 1u;
        } else {
            while (*(volatile unsigned*)&g_bar_gen == gen) { __nanosleep(32); }
        }
        __threadfence();
    }
    __syncthreads();
}

__global__ void __launch_bounds__(NT, 2) mega(
    const float* __restrict__ noise, const float* __restrict__ edge_attr,
    const int* __restrict__ eidx,
    const float* __restrict__ fc1_w, const float* __restrict__ fc1_b,
    const float* __restrict__ qw, const float* __restrict__ qb,
    const float* __restrict__ kw, const float* __restrict__ kb,
    const float* __restrict__ vw, const float* __restrict__ vb,
    const float* __restrict__ ew,
    const float* __restrict__ sw, const float* __restrict__ sb,
    const float* __restrict__ atom_w, const float* __restrict__ atom_b,
    const float* __restrict__ other_w, const float* __restrict__ other_b,
    const float* __restrict__ efw, const float* __restrict__ efb,
    float* __restrict__ out)
{
    __shared__ __align__(16) float smem[10912];   // 43.6KB union; 2 CTAs/SM = 87.2KB
    const int t = threadIdx.x, blk = blockIdx.x;
    const int w = t >> 5, lane = t & 31;

    // ================= init: x0 = relu(noise@fc1+b) broadcast; eid LUT =================
    if (blk < BB && t < HH) {
        float acc = fc1_b[t];
        #pragma unroll 4
        for (int i = 0; i < 128; i++) acc += noise[blk*128 + i] * fc1_w[i*HH + t];
        acc = fmaxf(acc, 0.f);
        for (int n = 0; n < NN; n++) g_bufA[(blk*NN + n)*HH + t] = acc;
    }
    { int e = blk*NT + t; if (e < NEdg) g_eid[eidx[e]*NN + eidx[NEdg + e]] = e; }
    grid_sync();

    float* xin = g_bufA;
    float* xout = g_bufB;

    for (int l = 0; l < LL; l++) {
        // ============ proj: [512,128] @ [qw|kw|vw|sw]; relu-on-load; skip -> xout ============
        if (blk < 208) {
            float (*As)[20] = (float(*)[20])smem;          // [64][20]
            float (*Bs)[64] = (float(*)[64])(smem + 1280); // [16][64]
            int ct = blk % 26, rt = blk / 26;
            const float* W; const float* bias; int ld, coff; float* outp;
            if (ct < 8)       { W = qw + l*HH*INNER; bias = qb + l*INNER; ld = INNER; coff = ct*64;      outp = g_q; }
            else if (ct < 16) { W = kw + l*HH*INNER; bias = kb + l*INNER; ld = INNER; coff = (ct-8)*64;  outp = g_k; }
            else if (ct < 24) { W = vw + l*HH*INNER; bias = vb + l*INNER; ld = INNER; coff = (ct-16)*64; outp = g_v; }
            else              { W = sw + l*HH*HH;    bias = sb + l*HH;    ld = HH;    coff = (ct-24)*64; outp = xout; }
            int tx = t & 15, ty = t >> 4;
            ull acc[4][4];
            #pragma unroll
            for (int r = 0; r < 4; r++)
                #pragma unroll
                for (int c = 0; c < 4; c++) acc[r][c] = 0ull;
            int r0 = rt*64;
            for (int k0 = 0; k0 < 128; k0 += 16) {
                int arow = t >> 2, akq = (t & 3) << 2;
                float4 a4 = *(const float4*)&xin[(r0+arow)*HH + k0 + akq];
                a4.x = fmaxf(a4.x, 0.f); a4.y = fmaxf(a4.y, 0.f);
                a4.z = fmaxf(a4.z, 0.f); a4.w = fmaxf(a4.w, 0.f);
                *(float4*)&As[arow][akq] = a4;
                int bkk = t >> 4, bn = (t & 15) << 2;
                *(float4*)&Bs[bkk][bn] = *(const float4*)&W[(k0+bkk)*ld + coff + bn];
                __syncthreads();
                #pragma unroll
                for (int kp = 0; kp < 8; kp++) {
                    ull a2[4], b2[4];
                    #pragma unroll
                    for (int r = 0; r < 4; r++) a2[r] = *(const ull*)&As[ty*4+r][kp*2];
                    #pragma unroll
                    for (int c = 0; c < 4; c++) b2[c] = pk2(Bs[kp*2][tx*4+c], Bs[kp*2+1][tx*4+c]);
                    #pragma unroll
                    for (int r = 0; r < 4; r++)
                        #pragma unroll
                        for (int c = 0; c < 4; c++) acc[r][c] = fma2(a2[r], b2[c], acc[r][c]);
                }
                __syncthreads();
            }
            #pragma unroll
            for (int r = 0; r < 4; r++)
                #pragma unroll
                for (int c = 0; c < 4; c++) {
                    int row = r0 + ty*4 + r, col = coff + tx*4 + c;
                    outp[row*ld + col] = f2sum(acc[r][c]) + bias[col];
                }
        }
        grid_sync();

        // ============ attn: job = blk = (b, h, jseg); red 0.25*agg into xout ============
        {
            float* sKV = smem;            // 8192: K pair-swizzled, then V linear
            float* sQ  = smem + 8192;     // 1024
            float* sEw = smem + 9216;     // 1024
            float (*sS)[68] = (float(*)[68])(smem + 10240);  // [8][68]
            float* sQE = smem + 10784;    // 64
            float* sAE = smem + 10848;    // 64
            int jseg = blk & 7;
            int h = (blk >> 3) & 3;
            int b = blk >> 5;
            int jbase = jseg * JB;
            const float scale = 0.08838834764831845f;  // 1/sqrt(128)

            {   // eW [8][128]
                int idx = t * 4;
                *(float4*)&sEw[idx] = *(const float4*)&ew[((size_t)l*EE + (idx >> 7))*INNER + h*HD + (idx & 127)];
            }
            {   // Q [8][128] linear
                int idx = t * 4;
                *(float4*)&sQ[idx] = *(const float4*)&g_q[(b*NN + jbase + (idx >> 7))*INNER + h*HD + (idx & 127)];
            }
            // K pair-swizzled: pair p of row r at sKV[r*128 + ((p ^ (r&31))<<1)]
            for (int q4 = t; q4 < NN*32; q4 += NT) {
                int row = q4 >> 5, dq = (q4 & 31) << 2;
                float4 v = *(const float4*)&g_k[(b*NN + row)*INNER + h*HD + dq];
                int rx = row & 31;
                float* base = &sKV[row*128];
                int p0 = ((dq >> 1) ^ rx) << 1;
                int p1 = (((dq >> 1) + 1) ^ rx) << 1;
                float2 lo = {v.x, v.y}, hi = {v.z, v.w};
                *(float2*)&base[p0] = lo;
                *(float2*)&base[p1] = hi;
            }
            __syncthreads();

            // scores: warp w -> dst row j=jbase+w; lane -> src i=lane, lane+32 (LDS.64, conflict-free)
            const float* qrow = &sQ[w*HD];
            float acc1, acc2;
            {
                const ull* q2 = (const ull*)qrow;
                const float* k1p = &sKV[lane*128];
                const float* k2p = &sKV[(lane+32)*128];
                ull a1 = 0ull, a2 = 0ull;
                #pragma unroll 8
                for (int d2 = 0; d2 < 64; d2++) {
                    ull qv = q2[d2];
                    int ds = (d2 ^ lane) << 1;
                    a1 = fma2(qv, *(const ull*)&k1p[ds], a1);
                    a2 = fma2(qv, *(const ull*)&k2p[ds], a2);
                }
                acc1 = f2sum(a1); acc2 = f2sum(a2);
            }
            // qe[j,f] = q[j]·eW[f]
            {
                int f = lane & 7, seg = lane >> 3;
                const float* ewrow = &sEw[f*HD + seg*32];
                const float* qseg  = qrow + seg*32;
                float p = 0.f;
                #pragma unroll
                for (int i = 0; i < 32; i++) {
                    int d = (i + lane) & 31;
                    p += qseg[d] * ewrow[d];
                }
                p += __shfl_xor_sync(0xffffffffu, p, 8);
                p += __shfl_xor_sync(0xffffffffu, p, 16);
                if (lane < 8) sQE[w*8 + lane] = p;
            }
            __syncwarp();

            // bias + mask + softmax + aggE (warp-local)
            int j = jbase + w;
            int i1 = lane, i2 = lane + 32;
            const float* eabase = edge_attr + (size_t)b * NEdg * EE;
            int e1 = (i1 == j) ? 0 : g_eid[i1*NN + j];
            int e2 = (i2 == j) ? 0 : g_eid[i2*NN + j];
            float4 ea1a = *(const float4*)&eabase[e1*EE];
            float4 ea1b = *(const float4*)&eabase[e1*EE + 4];
            float4 ea2a = *(const float4*)&eabase[e2*EE];
            float4 ea2b = *(const float4*)&eabase[e2*EE + 4];
            float ea1[8] = {ea1a.x, ea1a.y, ea1a.z, ea1a.w, ea1b.x, ea1b.y, ea1b.z, ea1b.w};
            float ea2[8] = {ea2a.x, ea2a.y, ea2a.z, ea2a.w, ea2b.x, ea2b.y, ea2b.z, ea2b.w};
            float bs1 = 0.f, bs2 = 0.f;
            #pragma unroll
            for (int f = 0; f < 8; f++) {
                float qe = sQE[w*8 + f];
                bs1 += ea1[f] * qe;
                bs2 += ea2[f] * qe;
            }
            float s1 = (i1 == j) ? -1e30f : (acc1 + bs1) * scale;
            float s2 = (i2 == j) ? -1e30f : (acc2 + bs2) * scale;
            float m = fmaxf(s1, s2);
            #pragma unroll
            for (int o = 1; o < 32; o <<= 1) m = fmaxf(m, __shfl_xor_sync(0xffffffffu, m, o));
            float x1 = __expf(s1 - m), x2 = __expf(s2 - m);
            float sum = x1 + x2;
            #pragma unroll
            for (int o = 1; o < 32; o <<= 1) sum += __shfl_xor_sync(0xffffffffu, sum, o);
            float inv = 1.f / sum;
            float al1 = x1 * inv, al2 = x2 * inv;
            sS[w][i1] = al1;
            sS[w][i2] = al2;
            {
                float ae[8];
                #pragma unroll
                for (int f = 0; f < 8; f++) {
                    float v = al1*ea1[f] + al2*ea2[f];
                    #pragma unroll
                    for (int o = 1; o < 32; o <<= 1) v += __shfl_xor_sync(0xffffffffu, v, o);
                    ae[f] = v;
                }
                if (lane == 0) {
                    #pragma unroll
                    for (int f = 0; f < 8; f++) sAE[w*8 + f] = ae[f];
                }
            }
            __syncthreads();

            // V (linear) into same buffer
            for (int idx = t*4; idx < NN*HD; idx += NT*4) {
                *(float4*)&sKV[idx] = *(const float4*)&g_v[(b*NN + (idx >> 7))*INNER + h*HD + (idx & 127)];
            }
            __syncthreads();

            // agg = alpha@V + aggE@eW ; red 0.25* into xout
            {
                int d0 = lane * 4;
                float ax = 0.f, ay = 0.f, az = 0.f, aw2 = 0.f;
                #pragma unroll 4
                for (int i = 0; i < NN; i++) {
                    float al = sS[w][i];
                    float4 v = *(const float4*)&sKV[i*HD + d0];
                    ax += al*v.x; ay += al*v.y; az += al*v.z; aw2 += al*v.w;
                }
                #pragma unroll
                for (int f = 0; f < 8; f++) {
                    float ae = sAE[w*8 + f];
                    float4 wv = *(const float4*)&sEw[f*HD + d0];
                    ax += ae*wv.x; ay += ae*wv.y; az += ae*wv.z; aw2 += ae*wv.w;
                }
                float* dst = &xout[(b*NN + j)*HH + d0];
                atomicAdd(dst+0, 0.25f*ax);
                atomicAdd(dst+1, 0.25f*ay);
                atomicAdd(dst+2, 0.25f*az);
                atomicAdd(dst+3, 0.25f*aw2);
            }
        }
        grid_sync();
        float* tmp = xin; xin = xout; xout = tmp;
    }

    // ================= node head + P/D (2 nodes per block) =================
    {
        float* xr   = smem;         // [2][128]
        float* outs = smem + 256;   // [2][40]
        float* red  = smem + 336;   // [2][2]
        int sub = t >> 7, tl = t & 127;
        int node = blk*2 + sub;
        xr[sub*128 + tl] = fmaxf(xin[node*128 + tl], 0.f);
        __syncthreads();
        if (tl < 40) {
            const float* xp = &xr[sub*128];
            float acc;
            if (tl < 9)       { acc = atom_b[tl];  for (int d = 0; d < HH; d++) acc += xp[d]*atom_w[d*9+tl]; }
            else if (tl < 24) { int c = tl-9;  acc = other_b[c]; for (int d = 0; d < HH; d++) acc += xp[d]*other_w[d*15+c]; }
            else if (tl < 32) { int f = tl-24; acc = 0.f; for (int d = 0; d < HH; d++) acc += xp[d]*efw[d*EE+f]; }
            else              { int f = tl-32; acc = 0.f; for (int d = 0; d < HH; d++) acc += xp[d]*efw[(128+d)*EE+f]; }
            outs[sub*40 + tl] = acc;
        }
        __syncthreads();
        if (tl == 0) {
            float m = -1e30f;
            for (int a = 0; a < 9; a++) m = fmaxf(m, outs[sub*40+a]);
            float s = 0.f;
            for (int a = 0; a < 9; a++) s += __expf(outs[sub*40+a]-m);
            red[sub*2] = m; red[sub*2+1] = s;
        }
        __syncthreads();
        if (tl < 9) {
            float p = __expf(outs[sub*40+tl]-red[sub*2]) / red[sub*2+1];
            out[node*24 + tl] = 1.f/(1.f + __expf(-p));
        } else if (tl < 24) {
            float o = 1.f/(1.f + __expf(-outs[sub*40+tl]));
            out[node*24 + tl] = 1.f/(1.f + __expf(-o));
        } else if (tl < 32) {
            g_P[node*EE + (tl-24)] = outs[sub*40+tl];
        } else if (tl < 40) {
            g_D[node*EE + (tl-32)] = outs[sub*40+tl];
        }
    }
    grid_sync();

    // ================= edge head: sigmoid(P[src] + D[dst] + b) =================
    if (t < 126) {
        int eg = blk*126 + t;     // 256*126 = 32256 exactly
        int b = eg / NEdg, e = eg % NEdg;
        int s = eidx[e], d = eidx[NEdg + e];
        const float* P = &g_P[(b*NN + s)*EE];
        const float* D = &g_D[(b*NN + d)*EE];
        float* o = out + (size_t)ROWS*24 + (size_t)eg*EE;
        #pragma unroll
        for (int f = 0; f < EE; f++) {
            float v = P[f] + D[f] + efb[f];
            o[f] = 1.f/(1.f + __expf(-v));
        }
    }
}

extern "C" void kernel_launch(void* const* d_in, const int* in_sizes, int n_in,
                              void* d_out, int out_size) {
    const float* noise     = (const float*)d_in[0];
    const float* edge_attr = (const float*)d_in[1];
    const int*   edge_index= (const int*)  d_in[2];
    const float* fc1_w     = (const float*)d_in[3];
    const float* fc1_b     = (const float*)d_in[4];
    const float* q_w       = (const float*)d_in[5];
    const float* q_b       = (const float*)d_in[6];
    const float* k_w       = (const float*)d_in[7];
    const float* k_b       = (const float*)d_in[8];
    const float* v_w       = (const float*)d_in[9];
    const float* v_b       = (const float*)d_in[10];
    const float* e_w       = (const float*)d_in[11];
    const float* skip_w    = (const float*)d_in[12];
    const float* skip_b    = (const float*)d_in[13];
    const float* atom_w    = (const float*)d_in[14];
    const float* atom_b    = (const float*)d_in[15];
    const float* other_w   = (const float*)d_in[16];
    const float* other_b   = (const float*)d_in[17];
    const float* efw       = (const float*)d_in[18];
    const float* efb       = (const float*)d_in[19];
    float* out = (float*)d_out;

    static bool configured = false;
    if (!configured) {
        cudaFuncSetAttribute(mega, cudaFuncAttributePreferredSharedMemoryCarveout, 100);
        configured = true;
    }

    mega<<<NB, NT>>>(noise, edge_attr, edge_index, fc1_w, fc1_b,
                     q_w, q_b, k_w, k_b, v_w, v_b, e_w, skip_w, skip_b,
                     atom_w, atom_b, other_w, other_b, efw, efb, out);
}

// round 6
// speedup vs baseline: 2.4578x; 1.1067x over previous
#include <cuda_runtime.h>
#include <math.h>

typedef unsigned long long ull;

#define BB 8
#define NN 64
#define HH 128
#define HEADS 4
#define HD 128
#define INNER 512
#define EE 8
#define NEdg 4032
#define LL 8
#define ROWS (BB*NN)   // 512
#define SPLITJ 8
#define JB (NN/SPLITJ) // 8
#define NB 256
#define NT 256

// ---------- persistent scratch ----------
__device__ float g_bufA[ROWS*HH];
__device__ float g_bufB[ROWS*HH];
__device__ float g_q[ROWS*INNER];
__device__ float g_k[ROWS*INNER];
__device__ float g_v[ROWS*INNER];
__device__ float g_P[ROWS*EE];
__device__ float g_D[ROWS*EE];
__device__ int   g_eid[NN*NN];
__device__ unsigned g_bar_cnt;
__device__ unsigned g_bar_gen;

// ---------- packed f32x2 helpers ----------
__device__ __forceinline__ ull fma2(ull a, ull b, ull c) {
    ull d; asm("fma.rn.f32x2 %0, %1, %2, %3;" : "=l"(d) : "l"(a), "l"(b), "l"(c)); return d;
}
__device__ __forceinline__ ull pk2(float x, float y) {
    ull r; unsigned a = __float_as_uint(x), b = __float_as_uint(y);
    asm("mov.b64 %0, {%1, %2};" : "=l"(r) : "r"(a), "r"(b)); return r;
}
__device__ __forceinline__ float f2sum(ull v) {
    unsigned a, b;
    asm("mov.b64 {%0, %1}, %2;" : "=r"(a), "=r"(b) : "l"(v));
    return __uint_as_float(a) + __uint_as_float(b);
}

// ---------- grid barrier ----------
__device__ __forceinline__ void grid_sync() {
    __syncthreads();
    if (threadIdx.x == 0) {
        __threadfence();
        unsigned gen = *(volatile unsigned*)&g_bar_gen;
        if (atomicAdd(&g_bar_cnt, 1u) == NB - 1) {
            *(volatile unsigned*)&g_bar_cnt = 0u;
            __threadfence();
            *(volatile unsigned*)&g_bar_gen = gen + 1u;
        } else {
            while (*(volatile unsigned*)&g_bar_gen == gen) { __nanosleep(32); }
        }
        __threadfence();
    }
    __syncthreads();
}

__global__ void __launch_bounds__(NT, 2) mega(
    const float* __restrict__ noise, const float* __restrict__ edge_attr,
    const int* __restrict__ eidx,
    const float* __restrict__ fc1_w, const float* __restrict__ fc1_b,
    const float* __restrict__ qw, const float* __restrict__ qb,
    const float* __restrict__ kw, const float* __restrict__ kb,
    const float* __restrict__ vw, const float* __restrict__ vb,
    const float* __restrict__ ew,
    const float* __restrict__ sw, const float* __restrict__ sb,
    const float* __restrict__ atom_w, const float* __restrict__ atom_b,
    const float* __restrict__ other_w, const float* __restrict__ other_b,
    const float* __restrict__ efw, const float* __restrict__ efb,
    float* __restrict__ out)
{
    __shared__ __align__(16) float smem[10912];   // 43.6KB; 2 CTAs/SM
    const int t = threadIdx.x, blk = blockIdx.x;
    const int w = t >> 5, lane = t & 31;

    // ================= init =================
    if (blk < BB && t < HH) {
        float acc = fc1_b[t];
        #pragma unroll 4
        for (int i = 0; i < 128; i++) acc += noise[blk*128 + i] * fc1_w[i*HH + t];
        acc = fmaxf(acc, 0.f);
        for (int n = 0; n < NN; n++) g_bufA[(blk*NN + n)*HH + t] = acc;
    }
    { int e = blk*NT + t; if (e < NEdg) g_eid[eidx[e]*NN + eidx[NEdg + e]] = e; }
    grid_sync();

    float* xin = g_bufA;
    float* xout = g_bufB;

    for (int l = 0; l < LL; l++) {
        // ============ proj: 64x64 tiles; double-buffered; pair-interleaved ull smem ============
        if (blk < 208) {
            ull* AsU = (ull*)smem;           // [2][8 kp][64 rows]
            ull* BsU = ((ull*)smem) + 1024;  // [2][8 kp][64 cols]
            int ct = blk % 26, rt = blk / 26;
            const float* W; const float* bias; int ld, coff; float* outp;
            if (ct < 8)       { W = qw + l*HH*INNER; bias = qb + l*INNER; ld = INNER; coff = ct*64;      outp = g_q; }
            else if (ct < 16) { W = kw + l*HH*INNER; bias = kb + l*INNER; ld = INNER; coff = (ct-8)*64;  outp = g_k; }
            else if (ct < 24) { W = vw + l*HH*INNER; bias = vb + l*INNER; ld = INNER; coff = (ct-16)*64; outp = g_v; }
            else              { W = sw + l*HH*HH;    bias = sb + l*HH;    ld = HH;    coff = (ct-24)*64; outp = xout; }
            const int tx = t & 15, ty = t >> 4;
            const int row_a = t & 63, kq = t >> 6;     // A loader: float4 along k
            const int col_b = t & 63, kpb = t >> 6;    // B loader: kp in {kpb, kpb+4}
            int r0 = rt*64;
            ull acc[4][4];
            #pragma unroll
            for (int r = 0; r < 4; r++)
                #pragma unroll
                for (int c = 0; c < 4; c++) acc[r][c] = 0ull;
            const float* arow_p = &xin[(r0+row_a)*HH + kq*4];
            const float* bcol_p = &W[coff + col_b];
            // prefetch k0 = 0
            float4 a4 = *(const float4*)arow_p;
            float bw0 = bcol_p[(2*kpb)*ld],     bw1 = bcol_p[(2*kpb+1)*ld];
            float bw2 = bcol_p[(2*kpb+8)*ld],   bw3 = bcol_p[(2*kpb+9)*ld];
            #pragma unroll
            for (int k0i = 0; k0i < 8; k0i++) {
                int bsel = (k0i & 1) << 9;
                AsU[bsel + (2*kq)*64 + row_a]   = pk2(fmaxf(a4.x,0.f), fmaxf(a4.y,0.f));
                AsU[bsel + (2*kq+1)*64 + row_a] = pk2(fmaxf(a4.z,0.f), fmaxf(a4.w,0.f));
                BsU[bsel + kpb*64 + col_b]      = pk2(bw0, bw1);
                BsU[bsel + (kpb+4)*64 + col_b]  = pk2(bw2, bw3);
                __syncthreads();
                if (k0i < 7) {
                    int k0 = (k0i+1)*16;
                    a4 = *(const float4*)(arow_p + k0);
                    bw0 = bcol_p[(k0 + 2*kpb)*ld];   bw1 = bcol_p[(k0 + 2*kpb+1)*ld];
                    bw2 = bcol_p[(k0 + 2*kpb+8)*ld]; bw3 = bcol_p[(k0 + 2*kpb+9)*ld];
                }
                const ull* Ab = AsU + bsel;
                const ull* Bb = BsU + bsel;
                #pragma unroll
                for (int kp = 0; kp < 8; kp++) {
                    ull a2[4], b2[4];
                    #pragma unroll
                    for (int r = 0; r < 4; r++) a2[r] = Ab[kp*64 + ty + 16*r];
                    #pragma unroll
                    for (int c = 0; c < 4; c++) b2[c] = Bb[kp*64 + tx + 16*c];
                    #pragma unroll
                    for (int r = 0; r < 4; r++)
                        #pragma unroll
                        for (int c = 0; c < 4; c++) acc[r][c] = fma2(a2[r], b2[c], acc[r][c]);
                }
            }
            #pragma unroll
            for (int r = 0; r < 4; r++)
                #pragma unroll
                for (int c = 0; c < 4; c++) {
                    int row = r0 + ty + 16*r, col = coff + tx + 16*c;
                    outp[row*ld + col] = f2sum(acc[r][c]) + bias[col];
                }
        }
        grid_sync();

        // ============ attn: 2 dst rows per reader warp; halved K/V smem traffic ============
        {
            float* sKV = smem;            // [64][128]: K swizzled, then V linear
            float* sQ  = smem + 8192;     // [8][128]
            float* sEw = smem + 9216;     // [8][128]
            float (*sS)[68] = (float(*)[68])(smem + 10240);
            float* sQE = smem + 10784;
            float* sAE = smem + 10848;
            int jseg = blk & 7;
            int h = (blk >> 3) & 3;
            int b = blk >> 5;
            int jbase = jseg * JB;
            const float scale = 0.08838834764831845f;  // 1/sqrt(128)

            {   // eW
                int idx = t * 4;
                *(float4*)&sEw[idx] = *(const float4*)&ew[((size_t)l*EE + (idx >> 7))*INNER + h*HD + (idx & 127)];
            }
            {   // Q
                int idx = t * 4;
                *(float4*)&sQ[idx] = *(const float4*)&g_q[(b*NN + jbase + (idx >> 7))*INNER + h*HD + (idx & 127)];
            }
            // K pair-swizzled: pair p of row r at sKV[r*128 + ((p ^ (r&31))<<1)]
            for (int q4 = t; q4 < NN*32; q4 += NT) {
                int row = q4 >> 5, dq = (q4 & 31) << 2;
                float4 v = *(const float4*)&g_k[(b*NN + row)*INNER + h*HD + dq];
                int rx = row & 31;
                float* base = &sKV[row*128];
                float2 lo = {v.x, v.y}, hi = {v.z, v.w};
                *(float2*)&base[((dq >> 1) ^ rx) << 1] = lo;
                *(float2*)&base[(((dq >> 1) + 1) ^ rx) << 1] = hi;
            }
            __syncthreads();

            // qe[w][f] = q[row w]·eW[f]
            {
                const float* qrow = &sQ[w*HD];
                int f = lane & 7, seg = lane >> 3;
                const float* ewrow = &sEw[f*HD + seg*32];
                const float* qseg  = qrow + seg*32;
                float p = 0.f;
                #pragma unroll
                for (int i = 0; i < 32; i++) {
                    int d = (i + lane) & 31;
                    p += qseg[d] * ewrow[d];
                }
                p += __shfl_xor_sync(0xffffffffu, p, 8);
                p += __shfl_xor_sync(0xffffffffu, p, 16);
                if (lane < 8) sQE[w*8 + lane] = p;
            }
            __syncthreads();

            // scores: warp (jp, ih); lane -> src i = ih*32+lane, rows 2jp, 2jp+1
            {
                int jp = w >> 1, ih = w & 1;
                int i = ih*32 + lane;
                int jl0 = jp*2, jl1 = jp*2 + 1;
                int j0 = jbase + jl0, j1 = jbase + jl1;
                const ull* q0p = (const ull*)&sQ[jl0*HD];
                const ull* q1p = (const ull*)&sQ[jl1*HD];
                const float* kr = &sKV[i*128];
                ull A0 = 0ull, A1 = 0ull;
                #pragma unroll 8
                for (int d2 = 0; d2 < 64; d2++) {
                    ull kv = *(const ull*)&kr[(d2 ^ lane) << 1];
                    A0 = fma2(q0p[d2], kv, A0);
                    A1 = fma2(q1p[d2], kv, A1);
                }
                float dot0 = f2sum(A0), dot1 = f2sum(A1);
                const float* eabase = edge_attr + (size_t)b * NEdg * EE;
                int e0 = (i == j0) ? 0 : g_eid[i*NN + j0];
                int e1 = (i == j1) ? 0 : g_eid[i*NN + j1];
                float4 p0a = *(const float4*)&eabase[e0*EE];
                float4 p0b = *(const float4*)&eabase[e0*EE + 4];
                float4 p1a = *(const float4*)&eabase[e1*EE];
                float4 p1b = *(const float4*)&eabase[e1*EE + 4];
                const float* qe0 = &sQE[jl0*8];
                const float* qe1 = &sQE[jl1*8];
                float bs0 = p0a.x*qe0[0] + p0a.y*qe0[1] + p0a.z*qe0[2] + p0a.w*qe0[3]
                          + p0b.x*qe0[4] + p0b.y*qe0[5] + p0b.z*qe0[6] + p0b.w*qe0[7];
                float bs1 = p1a.x*qe1[0] + p1a.y*qe1[1] + p1a.z*qe1[2] + p1a.w*qe1[3]
                          + p1b.x*qe1[4] + p1b.y*qe1[5] + p1b.z*qe1[6] + p1b.w*qe1[7];
                sS[jl0][i] = (i == j0) ? -1e30f : (dot0 + bs0) * scale;
                sS[jl1][i] = (i == j1) ? -1e30f : (dot1 + bs1) * scale;
            }
            __syncthreads();

            // V restage (issue LDG/STS early; readers wait for next sync)
            for (int idx = t*4; idx < NN*HD; idx += NT*4)
                *(float4*)&sKV[idx] = *(const float4*)&g_v[(b*NN + (idx >> 7))*INNER + h*HD + (idx & 127)];

            // softmax + aggE: warp w owns row w
            {
                int jg = jbase + w;
                float s1 = sS[w][lane], s2 = sS[w][lane + 32];
                float m = fmaxf(s1, s2);
                #pragma unroll
                for (int o = 1; o < 32; o <<= 1) m = fmaxf(m, __shfl_xor_sync(0xffffffffu, m, o));
                float x1 = __expf(s1 - m), x2 = __expf(s2 - m);
                float sum = x1 + x2;
                #pragma unroll
                for (int o = 1; o < 32; o <<= 1) sum += __shfl_xor_sync(0xffffffffu, sum, o);
                float inv = 1.f / sum;
                float al1 = x1 * inv, al2 = x2 * inv;
                sS[w][lane] = al1;
                sS[w][lane + 32] = al2;
                int i1 = lane, i2 = lane + 32;
                const float* eabase = edge_attr + (size_t)b * NEdg * EE;
                int e1 = (i1 == jg) ? 0 : g_eid[i1*NN + jg];
                int e2 = (i2 == jg) ? 0 : g_eid[i2*NN + jg];
                float4 ea1a = *(const float4*)&eabase[e1*EE];
                float4 ea1b = *(const float4*)&eabase[e1*EE + 4];
                float4 ea2a = *(const float4*)&eabase[e2*EE];
                float4 ea2b = *(const float4*)&eabase[e2*EE + 4];
                float ea1[8] = {ea1a.x, ea1a.y, ea1a.z, ea1a.w, ea1b.x, ea1b.y, ea1b.z, ea1b.w};
                float ea2[8] = {ea2a.x, ea2a.y, ea2a.z, ea2a.w, ea2b.x, ea2b.y, ea2b.z, ea2b.w};
                float ae[8];
                #pragma unroll
                for (int f = 0; f < 8; f++) {
                    float v = al1*ea1[f] + al2*ea2[f];
                    #pragma unroll
                    for (int o = 1; o < 32; o <<= 1) v += __shfl_xor_sync(0xffffffffu, v, o);
                    ae[f] = v;
                }
                if (lane == 0) {
                    #pragma unroll
                    for (int f = 0; f < 8; f++) sAE[w*8 + f] = ae[f];
                }
            }
            __syncthreads();

            // aggV: warp (jp2, dh); rows 2jp2, 2jp2+1; lane d = dh*64 + lane*2
            {
                int jp2 = w >> 1, dh = w & 1;
                int jl0 = jp2*2, jl1 = jl0 + 1;
                int d0 = dh*64 + lane*2;
                float a00 = 0.f, a01 = 0.f, a10 = 0.f, a11 = 0.f;
                #pragma unroll 4
                for (int i = 0; i < NN; i++) {
                    float al0 = sS[jl0][i], al1 = sS[jl1][i];
                    float2 v = *(const float2*)&sKV[i*HD + d0];
                    a00 += al0*v.x; a01 += al0*v.y;
                    a10 += al1*v.x; a11 += al1*v.y;
                }
                #pragma unroll
                for (int f = 0; f < 8; f++) {
                    float ae0 = sAE[jl0*8 + f], ae1 = sAE[jl1*8 + f];
                    float2 wv = *(const float2*)&sEw[f*HD + d0];
                    a00 += ae0*wv.x; a01 += ae0*wv.y;
                    a10 += ae1*wv.x; a11 += ae1*wv.y;
                }
                float* d0p = &xout[(b*NN + jbase + jl0)*HH + d0];
                float* d1p = &xout[(b*NN + jbase + jl1)*HH + d0];
                atomicAdd(d0p+0, 0.25f*a00);
                atomicAdd(d0p+1, 0.25f*a01);
                atomicAdd(d1p+0, 0.25f*a10);
                atomicAdd(d1p+1, 0.25f*a11);
            }
        }
        grid_sync();
        float* tmp = xin; xin = xout; xout = tmp;
    }

    // ================= node head + P/D (2 nodes per block) =================
    {
        float* xr   = smem;         // [2][128]
        float* outs = smem + 256;   // [2][40]
        float* red  = smem + 336;   // [2][2]
        int sub = t >> 7, tl = t & 127;
        int node = blk*2 + sub;
        xr[sub*128 + tl] = fmaxf(xin[node*128 + tl], 0.f);
        __syncthreads();
        if (tl < 40) {
            const float* xp = &xr[sub*128];
            float acc;
            if (tl < 9)       { acc = atom_b[tl];  for (int d = 0; d < HH; d++) acc += xp[d]*atom_w[d*9+tl]; }
            else if (tl < 24) { int c = tl-9;  acc = other_b[c]; for (int d = 0; d < HH; d++) acc += xp[d]*other_w[d*15+c]; }
            else if (tl < 32) { int f = tl-24; acc = 0.f; for (int d = 0; d < HH; d++) acc += xp[d]*efw[d*EE+f]; }
            else              { int f = tl-32; acc = 0.f; for (int d = 0; d < HH; d++) acc += xp[d]*efw[(128+d)*EE+f]; }
            outs[sub*40 + tl] = acc;
        }
        __syncthreads();
        if (tl == 0) {
            float m = -1e30f;
            for (int a = 0; a < 9; a++) m = fmaxf(m, outs[sub*40+a]);
            float s = 0.f;
            for (int a = 0; a < 9; a++) s += __expf(outs[sub*40+a]-m);
            red[sub*2] = m; red[sub*2+1] = s;
        }
        __syncthreads();
        if (tl < 9) {
            float p = __expf(outs[sub*40+tl]-red[sub*2]) / red[sub*2+1];
            out[node*24 + tl] = 1.f/(1.f + __expf(-p));
        } else if (tl < 24) {
            float o = 1.f/(1.f + __expf(-outs[sub*40+tl]));
            out[node*24 + tl] = 1.f/(1.f + __expf(-o));
        } else if (tl < 32) {
            g_P[node*EE + (tl-24)] = outs[sub*40+tl];
        } else if (tl < 40) {
            g_D[node*EE + (tl-32)] = outs[sub*40+tl];
        }
    }
    grid_sync();

    // ================= edge head =================
    if (t < 126) {
        int eg = blk*126 + t;     // 256*126 = 32256
        int b = eg / NEdg, e = eg % NEdg;
        int s = eidx[e], d = eidx[NEdg + e];
        const float* P = &g_P[(b*NN + s)*EE];
        const float* D = &g_D[(b*NN + d)*EE];
        float* o = out + (size_t)ROWS*24 + (size_t)eg*EE;
        #pragma unroll
        for (int f = 0; f < EE; f++) {
            float v = P[f] + D[f] + efb[f];
            o[f] = 1.f/(1.f + __expf(-v));
        }
    }
}

extern "C" void kernel_launch(void* const* d_in, const int* in_sizes, int n_in,
                              void* d_out, int out_size) {
    const float* noise     = (const float*)d_in[0];
    const float* edge_attr = (const float*)d_in[1];
    const int*   edge_index= (const int*)  d_in[2];
    const float* fc1_w     = (const float*)d_in[3];
    const float* fc1_b     = (const float*)d_in[4];
    const float* q_w       = (const float*)d_in[5];
    const float* q_b       = (const float*)d_in[6];
    const float* k_w       = (const float*)d_in[7];
    const float* k_b       = (const float*)d_in[8];
    const float* v_w       = (const float*)d_in[9];
    const float* v_b       = (const float*)d_in[10];
    const float* e_w       = (const float*)d_in[11];
    const float* skip_w    = (const float*)d_in[12];
    const float* skip_b    = (const float*)d_in[13];
    const float* atom_w    = (const float*)d_in[14];
    const float* atom_b    = (const float*)d_in[15];
    const float* other_w   = (const float*)d_in[16];
    const float* other_b   = (const float*)d_in[17];
    const float* efw       = (const float*)d_in[18];
    const float* efb       = (const float*)d_in[19];
    float* out = (float*)d_out;

    mega<<<NB, NT>>>(noise, edge_attr, edge_index, fc1_w, fc1_b,
                     q_w, q_b, k_w, k_b, v_w, v_b, e_w, skip_w, skip_b,
                     atom_w, atom_b, other_w, other_b, efw, efb, out);
}